// round 12
// baseline (speedup 1.0000x reference)
#include <cuda_runtime.h>
#include <cuda_fp16.h>
#include <cstdint>

#define BATCH     256
#define NLAB      30000
#define NEDGE     29999
#define NEDGE_PAD 30016              // multiple of 32; pad edges are (0,0) -> contribute 0
#define HID       1024
#define NBLK      296                // 148 SMs * 2 CTAs -> exactly one wave
#define BLKT      1024
#define CHUNK     32                 // edges per steal: 4 barrier-free rounds of 8
#define HALF      (NEDGE_PAD / 2)    // 15008, multiple of CHUNK
#define SMEM_BYTES (NLAB * 2)        // fp16 sigmoid row

// Persistent device state. Invariant: every kernel_launch leaves these in
// load-time state (g_acc=0, g_ctr=0, g_done=0), restored by the last CTA.
__device__ double       g_acc[3];           // [0]=bce, [1]=rec, [2]=prob
__device__ unsigned int g_edges[NEDGE_PAD]; // parent | (child<<16)
__device__ int          g_ctr;              // rec edge steal counter
__device__ unsigned int g_done;             // finished-CTA counter

// ---------------------------------------------------------------------------
// Multi-block pack with per-block dtype detection: odd 32-bit words < NEDGE
// are all zero iff data is int64 (values < 30000).
#define PACK_BLK 512
__global__ void __launch_bounds__(PACK_BLK) k_pack(const void* __restrict__ p,
                                                   const void* __restrict__ c)
{
    __shared__ int s_flag;
    int tid  = threadIdx.x;
    int base = blockIdx.x * PACK_BLK;
    if (tid == 0) s_flag = 0;
    __syncthreads();

    const unsigned int* pw = (const unsigned int*)p;
    const unsigned int* cw = (const unsigned int*)c;
    int i = base + tid;
    if ((i & 1) && i < NEDGE) {
        if ((pw[i] | cw[i]) != 0u) s_flag = 1;    // benign race
    }
    __syncthreads();
    bool is64 = (s_flag == 0);

    int e = base + tid;
    if (e < NEDGE_PAD) {
        unsigned int pk = 0;
        if (e < NEDGE) {
            unsigned int pv, cv;
            if (is64) {
                pv = (unsigned int)((const unsigned long long*)p)[e];
                cv = (unsigned int)((const unsigned long long*)c)[e];
            } else {
                pv = pw[e];
                cv = cw[e];
            }
            pk = pv | (cv << 16);
        }
        g_edges[e] = pk;
    }
}

// ---------------------------------------------------------------------------
__device__ __forceinline__ float block_reduce(float v, float* sbuf) {
    int lane = threadIdx.x & 31;
    int warp = threadIdx.x >> 5;
    #pragma unroll
    for (int o = 16; o > 0; o >>= 1) v += __shfl_down_sync(0xFFFFFFFFu, v, o);
    if (lane == 0) sbuf[warp] = v;
    __syncthreads();
    v = 0.f;
    if (warp == 0) {
        v = (lane < (BLKT >> 5)) ? sbuf[lane] : 0.f;
        #pragma unroll
        for (int o = 16; o > 0; o >>= 1) v += __shfl_down_sync(0xFFFFFFFFu, v, o);
    }
    return v;
}

__device__ __forceinline__ float fast_tanh(float x) {
    float r;
    asm("tanh.approx.f32 %0, %1;" : "=f"(r) : "f"(x));
    return r;
}

// softplus + sigmoid with 2 MUFU ops (tanh, lg2).
__device__ __forceinline__ void sig_sp(float x, float t_tgt,
                                       float& bacc, float& sig) {
    float a  = fabsf(x);
    float th = fast_tanh(0.5f * a);
    float u  = fmaf(0.5f, th, 0.5f);        // sigmoid(|x|) in [0.5, 1]
    bacc += fmaxf(x, 0.f) - __logf(u) - x * t_tgt;
    sig = (x >= 0.f) ? u : (1.f - u);
}

// ---------------------------------------------------------------------------
// Chunked block-level rec stealing (R9-proven shape). Processes every chunk
// it steals; returns once the stolen base has reached `limit` (no stolen
// work is ever discarded — a later call with a larger limit resumes).
// Termination: g_ctr is monotone, so base eventually >= limit for every CTA.
__device__ __forceinline__ float rec_steal(const float* __restrict__ params,
                                           int limit, int tid, int* s_base)
{
    int sub = tid >> 8;        // 0..3 : edge slot within a round
    int ln  = tid & 255;       // float4 lane within the 1024-dim row
    float racc = 0.f;
    for (;;) {
        __syncthreads();                    // protect s_base (WAR)
        if (tid == 0) *s_base = atomicAdd(&g_ctr, CHUNK);
        __syncthreads();
        const int base = *s_base;           // single uniform read per round
        if (base < NEDGE_PAD) {
            // NEDGE_PAD % CHUNK == 0 -> full chunk always in bounds
            for (int r = 0; r < CHUNK; r += 8) {
                #pragma unroll
                for (int k = 0; k < 2; k++) {
                    unsigned int pk = g_edges[base + r + k * 4 + sub];
                    const float4* pa = (const float4*)(params + (size_t)(pk & 0xFFFFu) * HID);
                    const float4* pb = (const float4*)(params + (size_t)(pk >> 16) * HID);
                    float4 a = pa[ln];
                    float4 c = pb[ln];
                    float dx = a.x - c.x, dy = a.y - c.y;
                    float dz = a.z - c.z, dw = a.w - c.w;
                    racc += dx * dx + dy * dy + dz * dz + dw * dw;
                }
            }
        }
        if (base + CHUNK >= limit) return racc;   // phase quota reached
    }
}

// ---------------------------------------------------------------------------
// Single-wave fused kernel with temporal phase staggering.
// Odd row-CTAs:  bce+prob first, then rec.
// Even row-CTAs: rec until the global counter passes HALF, then bce+prob,
//                then rejoin rec. Rec-only CTAs (b >= BATCH): rec throughout.
// This keeps ~168 CTAs on the L2-bound rec gather while ~128 CTAs stream
// DRAM at any time. Last CTA finalizes + resets globals (graph-replay safe).
__global__ void __launch_bounds__(BLKT, 2) k_main(
    const float* __restrict__ logits, const float* __restrict__ targets,
    const float* __restrict__ params, float* __restrict__ out)
{
    extern __shared__ __half s_sig[];       // NLAB fp16 sigmoids
    __shared__ float sbuf[BLKT >> 5];
    __shared__ int   s_base;

    int tid = threadIdx.x;
    int b   = blockIdx.x;

    bool row_cta   = (b < BATCH);
    bool rec_first = row_cta && ((b & 1) == 0);

    float bacc = 0.f, pacc = 0.f, racc = 0.f;

    if (rec_first)
        racc += rec_steal(params, HALF, tid, &s_base);

    if (row_cta) {
        const float4* l4 = (const float4*)(logits  + (size_t)b * NLAB);
        const float4* t4 = (const float4*)(targets + (size_t)b * NLAB);

        for (int i = tid; i < NLAB / 4; i += BLKT) {
            float4 x = __ldcs(l4 + i);      // streamed: keep params L2-resident
            float4 t = __ldcs(t4 + i);
            float s0, s1, s2, s3;
            sig_sp(x.x, t.x, bacc, s0);
            sig_sp(x.y, t.y, bacc, s1);
            sig_sp(x.z, t.z, bacc, s2);
            sig_sp(x.w, t.w, bacc, s3);
            __half2 h01 = __floats2half2_rn(s0, s1);
            __half2 h23 = __floats2half2_rn(s2, s3);
            uint2 pk;
            pk.x = *(unsigned int*)&h01;
            pk.y = *(unsigned int*)&h23;
            ((uint2*)s_sig)[i] = pk;
        }
        __syncthreads();

        // prob: 4 packed edges per uint4, no bounds checks (padded).
        const uint4* ge4 = (const uint4*)g_edges;
        for (int i = tid; i < NEDGE_PAD / 4; i += BLKT) {
            uint4 q = ge4[i];
            #pragma unroll
            for (int k = 0; k < 4; k++) {
                unsigned int pk = (&q.x)[k];
                float sp = __half2float(s_sig[pk & 0xFFFFu]);
                float sc = __half2float(s_sig[pk >> 16]);
                pacc += fmaxf(sc - sp, 0.f);
            }
        }
    }

    // rec until exhausted (odd/rec-only CTAs start here; even CTAs resume)
    racc += rec_steal(params, NEDGE_PAD, tid, &s_base);

    // ---- reductions (uniform across the CTA) ----
    if (row_cta) {
        float bt = block_reduce(bacc, sbuf);
        if (tid == 0) atomicAdd(&g_acc[0], (double)bt);
        __syncthreads();
        float pt = block_reduce(pacc, sbuf);
        if (tid == 0) atomicAdd(&g_acc[2], (double)pt);
        __syncthreads();
    }
    float rt = block_reduce(racc, sbuf);
    if (tid == 0) atomicAdd(&g_acc[1], (double)rt);

    // ---- finalize: last CTA writes out and resets globals ----
    if (tid == 0) {
        __threadfence();                     // publish this CTA's atomics
        unsigned int d = atomicAdd(&g_done, 1u);
        if (d == NBLK - 1) {
            __threadfence();                 // acquire others' g_acc
            volatile double* acc = g_acc;
            double bce  = acc[0] / ((double)BATCH * (double)NLAB);
            double rec  = 0.5 * acc[1];
            double prob = acc[2];
            out[0] = (float)(bce + 1e-4 * rec + 1e-4 * prob);
            g_acc[0] = 0.0; g_acc[1] = 0.0; g_acc[2] = 0.0;
            g_ctr  = 0;
            g_done = 0u;
            __threadfence();
        }
    }
}

// ---------------------------------------------------------------------------
extern "C" void kernel_launch(void* const* d_in, const int* in_sizes, int n_in,
                              void* d_out, int out_size)
{
    const float* logits  = (const float*)d_in[0];
    const float* targets = (const float*)d_in[1];
    const float* params  = (const float*)d_in[2];
    const void*  parent  = d_in[3];
    const void*  child   = d_in[4];

    cudaFuncSetAttribute(k_main,
                         cudaFuncAttributeMaxDynamicSharedMemorySize,
                         SMEM_BYTES);

    k_pack<<<(NEDGE_PAD + PACK_BLK - 1) / PACK_BLK, PACK_BLK>>>(parent, child);
    k_main<<<NBLK, BLKT, SMEM_BYTES>>>(logits, targets, params, (float*)d_out);
}

// round 14
// speedup vs baseline: 1.0872x; 1.0872x over previous
#include <cuda_runtime.h>
#include <cuda_fp16.h>
#include <cstdint>

#define BATCH     256
#define NLAB      30000
#define NEDGE     29999
#define NEDGE_PAD 30016              // multiple of 32; pad edges are (0,0) -> contribute 0
#define HID       1024
#define NBLK      296                // 148 SMs * 2 CTAs -> exactly one wave
#define BLKT      1024
#define CHUNK     32                 // edges per steal: 4 barrier-free rounds of 8
#define SMEM_BYTES (NLAB * 2)        // fp16 sigmoid row

// Persistent device state. Invariant: every kernel_launch leaves these in
// load-time state (g_acc=0, g_ctr=0, g_done=0), restored by the last CTA.
__device__ double       g_acc[3];           // [0]=bce, [1]=rec, [2]=prob
__device__ unsigned int g_edges[NEDGE_PAD]; // parent | (child<<16)
__device__ int          g_ctr;              // rec edge steal counter
__device__ unsigned int g_done;             // finished-CTA counter

// ---------------------------------------------------------------------------
// Multi-block pack with per-block dtype detection: odd 32-bit words < NEDGE
// are all zero iff data is int64 (values < 30000).
#define PACK_BLK 512
__global__ void __launch_bounds__(PACK_BLK) k_pack(const void* __restrict__ p,
                                                   const void* __restrict__ c)
{
    __shared__ int s_flag;
    int tid  = threadIdx.x;
    int base = blockIdx.x * PACK_BLK;
    if (tid == 0) s_flag = 0;
    __syncthreads();

    const unsigned int* pw = (const unsigned int*)p;
    const unsigned int* cw = (const unsigned int*)c;
    int i = base + tid;
    if ((i & 1) && i < NEDGE) {
        if ((pw[i] | cw[i]) != 0u) s_flag = 1;    // benign race
    }
    __syncthreads();
    bool is64 = (s_flag == 0);

    int e = base + tid;
    if (e < NEDGE_PAD) {
        unsigned int pk = 0;
        if (e < NEDGE) {
            unsigned int pv, cv;
            if (is64) {
                pv = (unsigned int)((const unsigned long long*)p)[e];
                cv = (unsigned int)((const unsigned long long*)c)[e];
            } else {
                pv = pw[e];
                cv = cw[e];
            }
            pk = pv | (cv << 16);
        }
        g_edges[e] = pk;
    }
}

// ---------------------------------------------------------------------------
__device__ __forceinline__ float block_reduce(float v, float* sbuf) {
    int lane = threadIdx.x & 31;
    int warp = threadIdx.x >> 5;
    #pragma unroll
    for (int o = 16; o > 0; o >>= 1) v += __shfl_down_sync(0xFFFFFFFFu, v, o);
    if (lane == 0) sbuf[warp] = v;
    __syncthreads();
    v = 0.f;
    if (warp == 0) {
        v = (lane < (BLKT >> 5)) ? sbuf[lane] : 0.f;
        #pragma unroll
        for (int o = 16; o > 0; o >>= 1) v += __shfl_down_sync(0xFFFFFFFFu, v, o);
    }
    return v;
}

__device__ __forceinline__ float fast_tanh(float x) {
    float r;
    asm("tanh.approx.f32 %0, %1;" : "=f"(r) : "f"(x));
    return r;
}

// softplus + sigmoid with 2 MUFU ops (tanh, lg2).
__device__ __forceinline__ void sig_sp(float x, float t_tgt,
                                       float& bacc, float& sig) {
    float a  = fabsf(x);
    float th = fast_tanh(0.5f * a);
    float u  = fmaf(0.5f, th, 0.5f);        // sigmoid(|x|) in [0.5, 1]
    bacc += fmaxf(x, 0.f) - __logf(u) - x * t_tgt;
    sig = (x >= 0.f) ? u : (1.f - u);
}

// ---------------------------------------------------------------------------
// Single-wave fused kernel (R9 flow). Blocks [0,BATCH): bce + prob for one
// batch row, then join rec chunked work stealing. Blocks [BATCH,NBLK): rec
// from the start. Rec rounds read edge words from a per-chunk smem stage so
// the row-address dependency chain starts at LDS (29cyc) instead of LDG
// (234+cyc). Last CTA finalizes + resets globals (graph-replay safe).
__global__ void __launch_bounds__(BLKT, 2) k_main(
    const float* __restrict__ logits, const float* __restrict__ targets,
    const float* __restrict__ params, float* __restrict__ out)
{
    extern __shared__ __half s_sig[];       // NLAB fp16 sigmoids
    __shared__ float        sbuf[BLKT >> 5];
    __shared__ int          s_base;
    __shared__ unsigned int s_edge[CHUNK];  // staged edge words for the chunk

    int tid = threadIdx.x;
    int b   = blockIdx.x;

    if (b < BATCH) {
        const float4* l4 = (const float4*)(logits  + (size_t)b * NLAB);
        const float4* t4 = (const float4*)(targets + (size_t)b * NLAB);

        float bacc = 0.f;
        for (int i = tid; i < NLAB / 4; i += BLKT) {
            float4 x = __ldcs(l4 + i);      // streamed: keep params L2-resident
            float4 t = __ldcs(t4 + i);
            float s0, s1, s2, s3;
            sig_sp(x.x, t.x, bacc, s0);
            sig_sp(x.y, t.y, bacc, s1);
            sig_sp(x.z, t.z, bacc, s2);
            sig_sp(x.w, t.w, bacc, s3);
            __half2 h01 = __floats2half2_rn(s0, s1);
            __half2 h23 = __floats2half2_rn(s2, s3);
            uint2 pk;
            pk.x = *(unsigned int*)&h01;
            pk.y = *(unsigned int*)&h23;
            ((uint2*)s_sig)[i] = pk;
        }
        __syncthreads();

        // prob: 4 packed edges per uint4, no bounds checks (padded).
        float pacc = 0.f;
        const uint4* ge4 = (const uint4*)g_edges;
        for (int i = tid; i < NEDGE_PAD / 4; i += BLKT) {
            uint4 q = ge4[i];
            #pragma unroll
            for (int k = 0; k < 4; k++) {
                unsigned int pk = (&q.x)[k];
                float sp = __half2float(s_sig[pk & 0xFFFFu]);
                float sc = __half2float(s_sig[pk >> 16]);
                pacc += fmaxf(sc - sp, 0.f);
            }
        }

        float bt = block_reduce(bacc, sbuf);
        if (tid == 0) atomicAdd(&g_acc[0], (double)bt);
        __syncthreads();
        float pt = block_reduce(pacc, sbuf);
        if (tid == 0) atomicAdd(&g_acc[2], (double)pt);
        __syncthreads();
    }

    // ---- rec: chunked block-level work stealing with smem edge staging.
    // One atomic + three barriers per CHUNK edges; the CHUNK/8 rounds inside
    // a chunk are barrier-free, and edge words come from smem so row loads
    // issue ~200 cycles earlier each round.
    int sub = tid >> 8;        // 0..3 : edge slot within a round
    int ln  = tid & 255;       // float4 lane within the 1024-dim row
    float racc = 0.f;
    for (;;) {
        __syncthreads();                    // protect s_base/s_edge (WAR)
        if (tid == 0) s_base = atomicAdd(&g_ctr, CHUNK);
        __syncthreads();
        const int base = s_base;
        if (base >= NEDGE_PAD) break;
        if (tid < CHUNK) s_edge[tid] = g_edges[base + tid];
        __syncthreads();
        // NEDGE_PAD % CHUNK == 0 -> full chunk always in bounds
        for (int r = 0; r < CHUNK; r += 8) {
            #pragma unroll
            for (int k = 0; k < 2; k++) {
                unsigned int pk = s_edge[r + k * 4 + sub];
                const float4* pa = (const float4*)(params + (size_t)(pk & 0xFFFFu) * HID);
                const float4* pb = (const float4*)(params + (size_t)(pk >> 16) * HID);
                float4 a = pa[ln];
                float4 c = pb[ln];
                float dx = a.x - c.x, dy = a.y - c.y;
                float dz = a.z - c.z, dw = a.w - c.w;
                racc += dx * dx + dy * dy + dz * dz + dw * dw;
            }
        }
    }
    float rt = block_reduce(racc, sbuf);
    if (tid == 0) atomicAdd(&g_acc[1], (double)rt);

    // ---- finalize: last CTA writes out and resets globals ----
    if (tid == 0) {
        __threadfence();                     // publish this CTA's atomics
        unsigned int d = atomicAdd(&g_done, 1u);
        if (d == NBLK - 1) {
            __threadfence();                 // acquire others' g_acc
            volatile double* acc = g_acc;
            double bce  = acc[0] / ((double)BATCH * (double)NLAB);
            double rec  = 0.5 * acc[1];
            double prob = acc[2];
            out[0] = (float)(bce + 1e-4 * rec + 1e-4 * prob);
            g_acc[0] = 0.0; g_acc[1] = 0.0; g_acc[2] = 0.0;
            g_ctr  = 0;
            g_done = 0u;
            __threadfence();
        }
    }
}

// ---------------------------------------------------------------------------
extern "C" void kernel_launch(void* const* d_in, const int* in_sizes, int n_in,
                              void* d_out, int out_size)
{
    const float* logits  = (const float*)d_in[0];
    const float* targets = (const float*)d_in[1];
    const float* params  = (const float*)d_in[2];
    const void*  parent  = d_in[3];
    const void*  child   = d_in[4];

    cudaFuncSetAttribute(k_main,
                         cudaFuncAttributeMaxDynamicSharedMemorySize,
                         SMEM_BYTES);

    k_pack<<<(NEDGE_PAD + PACK_BLK - 1) / PACK_BLK, PACK_BLK>>>(parent, child);
    k_main<<<NBLK, BLKT, SMEM_BYTES>>>(logits, targets, params, (float*)d_out);
}